// round 8
// baseline (speedup 1.0000x reference)
#include <cuda_runtime.h>
#include <cuda_fp16.h>
#include <math.h>
#include <stdint.h>

#define B 2
#define T 2048
#define V 32000
#define D 1024
#define DF 4096
#define L 6
#define BT (B*T)

// ---------------- scratch (device globals; no allocation allowed) ----------
__device__ __align__(1024) float  g_x[(size_t)BT * D];
__device__ __align__(1024) __half g_x16[(size_t)BT * D];
__device__ __align__(1024) __half g_qkv16[(size_t)3 * BT * D];
__device__ __align__(1024) __half g_v16T[(size_t)BT * D];
__device__ __align__(1024) float  g_attn[(size_t)BT * D];
__device__ __align__(1024) float  g_scores[(size_t)B * T * T];
__device__ __align__(1024) __half g_probs16[(size_t)B * T * T];
__device__ __align__(1024) __half g_h16[(size_t)BT * DF];
__device__ __align__(1024) __half g_wqkv16[(size_t)L * 3 * D * D];
__device__ __align__(1024) __half g_w1T16[(size_t)L * DF * D];
__device__ __align__(1024) __half g_w2T16[(size_t)L * D * DF];
__device__ __align__(1024) __half g_wout16[(size_t)V * D];

// ---------------- low-level helpers -----------------------------------------
__device__ __forceinline__ uint32_t smem_u32(const void* p) {
    uint32_t a;
    asm("{ .reg .u64 t; cvta.to.shared.u64 t, %1; cvt.u32.u64 %0, t; }" : "=r"(a) : "l"(p));
    return a;
}
__device__ __forceinline__ void cp16(void* smem_dst, const void* gmem_src) {
    uint32_t s = (uint32_t)__cvta_generic_to_shared(smem_dst);
    asm volatile("cp.async.cg.shared.global [%0], [%1], 16;" :: "r"(s), "l"(gmem_src));
}
__device__ __forceinline__ void cp_commit() {
    asm volatile("cp.async.commit_group;" ::: "memory");
}
template<int N>
__device__ __forceinline__ void cp_wait() {
    asm volatile("cp.async.wait_group %0;" :: "n"(N) : "memory");
}
__device__ __forceinline__ void ldsm4(uint32_t addr, uint32_t& r0, uint32_t& r1,
                                      uint32_t& r2, uint32_t& r3) {
    asm volatile("ldmatrix.sync.aligned.m8n8.x4.shared.b16 {%0,%1,%2,%3}, [%4];"
                 : "=r"(r0), "=r"(r1), "=r"(r2), "=r"(r3) : "r"(addr));
}

__device__ __forceinline__ float block_sum(float v, float* red) {
    int tid = threadIdx.x, lane = tid & 31, warp = tid >> 5;
    int nw = blockDim.x >> 5;
    #pragma unroll
    for (int o = 16; o; o >>= 1) v += __shfl_xor_sync(0xffffffffu, v, o);
    if (lane == 0) red[warp] = v;
    __syncthreads();
    float r = (tid < nw) ? red[tid] : 0.0f;
    if (warp == 0) {
        #pragma unroll
        for (int o = 16; o; o >>= 1) r += __shfl_xor_sync(0xffffffffu, r, o);
        if (tid == 0) red[0] = r;
    }
    __syncthreads();
    float out = red[0];
    __syncthreads();
    return out;
}
__device__ __forceinline__ float block_max(float v, float* red) {
    int tid = threadIdx.x, lane = tid & 31, warp = tid >> 5;
    int nw = blockDim.x >> 5;
    #pragma unroll
    for (int o = 16; o; o >>= 1) v = fmaxf(v, __shfl_xor_sync(0xffffffffu, v, o));
    if (lane == 0) red[warp] = v;
    __syncthreads();
    float r = (tid < nw) ? red[tid] : -INFINITY;
    if (warp == 0) {
        #pragma unroll
        for (int o = 16; o; o >>= 1) r = fmaxf(r, __shfl_xor_sync(0xffffffffu, r, o));
        if (tid == 0) red[0] = r;
    }
    __syncthreads();
    float out = red[0];
    __syncthreads();
    return out;
}

// ---------------- embed + positional encoding -------------------------------
__global__ void embed_pe_kernel(const int* __restrict__ tokens,
                                const float* __restrict__ embed,
                                float* __restrict__ x, __half* __restrict__ x16) {
    const int row = blockIdx.x;
    const int t = row % T;
    const int tok = tokens[row];
    const float* erow = embed + (size_t)tok * D;
    float* xrow = x + (size_t)row * D;
    __half* xrow16 = x16 + (size_t)row * D;
    for (int i = threadIdx.x; i < D; i += blockDim.x) {
        int ip = i & ~1;
        double freq = exp(((double)ip / (double)D) * log(10000.0));
        double angle = (double)t / freq;
        float pe = (i & 1) ? (float)cos(angle) : (float)sin(angle);
        float v = erow[i] + pe;
        xrow[i] = v;
        xrow16[i] = __float2half(v);
    }
}

// ---------------- transpose fp32 -> fp16 [R,C] -> [C,R], batched -------------
__global__ void transpose_f2h_kernel(const float* __restrict__ in, __half* __restrict__ out,
                                     int R, int C, long inStride, long outStride) {
    __shared__ float tile[32][33];
    const long zi = blockIdx.z;
    in  += zi * inStride;
    out += zi * outStride;
    const int c0 = blockIdx.x * 32, r0 = blockIdx.y * 32;
    const int tx = threadIdx.x, ty = threadIdx.y;   // 32 x 8
    #pragma unroll
    for (int j = 0; j < 32; j += 8)
        tile[ty + j][tx] = in[(long)(r0 + ty + j) * C + c0 + tx];
    __syncthreads();
    #pragma unroll
    for (int j = 0; j < 32; j += 8)
        out[(long)(c0 + ty + j) * R + r0 + tx] = __float2half(tile[tx][ty + j]);
}

// ---------------- transpose fp16 -> fp16 [R,C] -> [C,R], batched -------------
__global__ void transpose_h2h_kernel(const __half* __restrict__ in, __half* __restrict__ out,
                                     int R, int C, long inStride, long outStride) {
    __shared__ __half tile[32][36];
    const long zi = blockIdx.z;
    in  += zi * inStride;
    out += zi * outStride;
    const int c0 = blockIdx.x * 32, r0 = blockIdx.y * 32;
    const int tx = threadIdx.x, ty = threadIdx.y;   // 32 x 8
    #pragma unroll
    for (int j = 0; j < 32; j += 8)
        tile[ty + j][tx] = in[(long)(r0 + ty + j) * C + c0 + tx];
    __syncthreads();
    #pragma unroll
    for (int j = 0; j < 32; j += 8)
        out[(long)(c0 + ty + j) * R + r0 + tx] = tile[tx][ty + j];
}

// ---------------- FP16 mma.sync TT GEMM --------------------------------------
// C[M,N] = A[M,K] @ Bt[N,K]^T (+bias)(+relu). A,Bt fp16 K-major, fp32 accum.
// BM=128, BN template (128: 8 warps 4x2, warp 32x64; 256: 8 warps 2x4, warp 64x64).
// BK=32 (2x k16), 3-stage cp.async.
// CAUSAL: 0 none, 1 skip tiles above diagonal, 2 K truncated at bm+128.
#define RST 40                                  // halves per smem row (80 B)

template<int CAUSAL, bool RELU, bool BIAS, bool OUT16, int BN>
__global__ __launch_bounds__(256, (BN == 128) ? 2 : 1) void gemm16(
    const __half* __restrict__ A, const __half* __restrict__ Bt,
    const float* __restrict__ b0, const float* __restrict__ b1, const float* __restrict__ b2,
    void* __restrict__ Cv, int N, int K, long sA, long sB, long sC)
{
    constexpr int BM = 128;
    constexpr int WM = (BN == 128) ? 32 : 64;
    constexpr int MI = WM / 16;                  // 2 or 4
    constexpr int STAGE_H = (BM + BN) * RST;     // halves per stage

    extern __shared__ __half smh[];

    const int bm = blockIdx.y * BM;
    const int bn = blockIdx.x * BN;
    if (CAUSAL == 1 && bn > bm + BM - 1) return;
    const int z = blockIdx.z;
    A  += (long)z * sA;
    Bt += (long)z * sB;

    const int tid = threadIdx.x, warp = tid >> 5, lane = tid & 31;
    const int g = lane >> 2, cg = lane & 3;
    const int wm = (BN == 128) ? (warp >> 1) * 32 : (warp >> 2) * 64;
    const int wn = (BN == 128) ? (warp & 1) * 64 : (warp & 3) * 64;

    const int Kend = (CAUSAL == 2) ? min(K, bm + BM) : K;
    const int KT = Kend >> 5;

    const uint32_t sbase = smem_u32(smh);

    // ldmatrix.x4 per-lane byte offsets within a stage (canonical m16n8k16 map)
    uint32_t aoff[MI], boff[4];
    #pragma unroll
    for (int mi = 0; mi < MI; mi++)
        aoff[mi] = (uint32_t)((wm + mi * 16 + (lane & 15)) * RST * 2 + (lane >> 4) * 16);
    #pragma unroll
    for (int np = 0; np < 4; np++)
        boff[np] = (uint32_t)((BM + wn + np * 16 + (lane & 15)) * RST * 2 + (lane >> 4) * 16);

    auto issue = [&](int s) {
        if (s >= KT) { cp_commit(); return; }
        const int k0 = s << 5;
        __half* As = smh + (s % 3) * STAGE_H;
        __half* Bs = As + BM * RST;
        #pragma unroll
        for (int i = 0; i < 2; i++) {
            int idx = tid + i * 256;
            int r = idx >> 2, c = (idx & 3) * 8;
            cp16(&As[r * RST + c], A + (long)(bm + r) * K + k0 + c);
        }
        #pragma unroll
        for (int i = 0; i < BN / 64; i++) {
            int idx = tid + i * 256;
            int r = idx >> 2, c = (idx & 3) * 8;
            cp16(&Bs[r * RST + c], Bt + (long)(bn + r) * K + k0 + c);
        }
        cp_commit();
    };

    float acc[MI][8][4];
    #pragma unroll
    for (int mi = 0; mi < MI; mi++)
        #pragma unroll
        for (int ni = 0; ni < 8; ni++)
            #pragma unroll
            for (int j = 0; j < 4; j++) acc[mi][ni][j] = 0.0f;

    auto comp = [&](int slot) {
        const uint32_t st = sbase + (uint32_t)slot * (STAGE_H * 2);
        #pragma unroll
        for (int ks = 0; ks < 2; ks++) {
            uint32_t af[MI][4];
            uint32_t bf[8][2];
            #pragma unroll
            for (int mi = 0; mi < MI; mi++)
                ldsm4(st + aoff[mi] + ks * 32, af[mi][0], af[mi][1], af[mi][2], af[mi][3]);
            #pragma unroll
            for (int np = 0; np < 4; np++) {
                uint32_t q0, q1, q2, q3;
                ldsm4(st + boff[np] + ks * 32, q0, q1, q2, q3);
                bf[2 * np][0] = q0; bf[2 * np][1] = q2;
                bf[2 * np + 1][0] = q1; bf[2 * np + 1][1] = q3;
            }
            #pragma unroll
            for (int mi = 0; mi < MI; mi++)
                #pragma unroll
                for (int ni = 0; ni < 8; ni++)
                    asm volatile(
                        "mma.sync.aligned.m16n8k16.row.col.f32.f16.f16.f32 "
                        "{%0,%1,%2,%3}, {%4,%5,%6,%7}, {%8,%9}, {%0,%1,%2,%3};"
                        : "+f"(acc[mi][ni][0]), "+f"(acc[mi][ni][1]),
                          "+f"(acc[mi][ni][2]), "+f"(acc[mi][ni][3])
                        : "r"(af[mi][0]), "r"(af[mi][1]), "r"(af[mi][2]), "r"(af[mi][3]),
                          "r"(bf[ni][0]), "r"(bf[ni][1]));
        }
    };

    issue(0);
    issue(1);
    for (int i = 0; i < KT; i++) {
        cp_wait<1>();
        __syncthreads();
        issue(i + 2);
        comp(i % 3);
    }

    // epilogue
    const float* bias = BIAS ? (z == 0 ? b0 : (z == 1 ? b1 : b2)) : b0;
    float*  Cf = (float*)Cv  + (long)z * sC;
    __half* Ch = (__half*)Cv + (long)z * sC;
    #pragma unroll
    for (int mi = 0; mi < MI; mi++) {
        const long r0 = bm + wm + mi * 16 + g;
        #pragma unroll
        for (int ni = 0; ni < 8; ni++) {
            const int col = bn + wn + ni * 8 + cg * 2;
            float bb0 = 0.0f, bb1 = 0.0f;
            if (BIAS) { bb0 = bias[col]; bb1 = bias[col + 1]; }
            float2 v0 = make_float2(acc[mi][ni][0] + bb0, acc[mi][ni][1] + bb1);
            float2 v1 = make_float2(acc[mi][ni][2] + bb0, acc[mi][ni][3] + bb1);
            if (RELU) {
                v0.x = fmaxf(v0.x, 0.0f); v0.y = fmaxf(v0.y, 0.0f);
                v1.x = fmaxf(v1.x, 0.0f); v1.y = fmaxf(v1.y, 0.0f);
            }
            if (OUT16) {
                *(__half2*)(Ch + r0 * N + col)       = __floats2half2_rn(v0.x, v0.y);
                *(__half2*)(Ch + (r0 + 8) * N + col) = __floats2half2_rn(v1.x, v1.y);
            } else {
                *(float2*)(Cf + r0 * N + col)       = v0;
                *(float2*)(Cf + (r0 + 8) * N + col) = v1;
            }
        }
    }
}

#define SMEM128 (3 * (256 * RST) * 2)   // 61440
#define SMEM256 (3 * (384 * RST) * 2)   // 92160

// ---------------- causal softmax: fp32 scores -> fp16 probs ------------------
__global__ void softmax_causal_kernel(const float* __restrict__ scores,
                                      __half* __restrict__ probs) {
    const int t = blockIdx.x;
    const int b = blockIdx.y;
    const float* row = scores + ((size_t)b * T + t) * T;
    __half* prow = probs + ((size_t)b * T + t) * T;
    const int n = t + 1;
    const float inv_scale = 0.03125f;   // 1/sqrt(1024)
    __shared__ float red[32];
    const int tid = threadIdx.x;

    float m = -INFINITY;
    for (int s = tid; s < n; s += blockDim.x) m = fmaxf(m, row[s] * inv_scale);
    m = block_max(m, red);

    float sum = 0.0f;
    for (int s = tid; s < n; s += blockDim.x) sum += expf(row[s] * inv_scale - m);
    sum = block_sum(sum, red);
    const float inv = 1.0f / sum;

    for (int s = tid; s < n; s += blockDim.x)
        prow[s] = __float2half(expf(row[s] * inv_scale - m) * inv);
    for (int s = n + tid; s < T; s += blockDim.x) prow[s] = __float2half(0.0f);
}

// ---------------- x = LayerNorm(x + y) * g + beta  (fp32 + fp16 out) ---------
__global__ void add_ln_kernel(float* __restrict__ x, __half* __restrict__ x16,
                              const float* __restrict__ y,
                              const float* __restrict__ g, const float* __restrict__ beta) {
    const int row = blockIdx.x;
    __shared__ float buf[D];
    __shared__ float red[32];
    float* xr = x + (size_t)row * D;
    __half* xr16 = x16 + (size_t)row * D;
    const float* yr = y + (size_t)row * D;
    const int tid = threadIdx.x;

    float sum = 0.0f;
    for (int i = tid; i < D; i += blockDim.x) {
        float v = xr[i] + yr[i];
        buf[i] = v;
        sum += v;
    }
    __syncthreads();
    sum = block_sum(sum, red);
    const float mu = sum * (1.0f / D);

    float vs = 0.0f;
    for (int i = tid; i < D; i += blockDim.x) {
        float d = buf[i] - mu;
        vs += d * d;
    }
    vs = block_sum(vs, red);
    const float rstd = rsqrtf(vs * (1.0f / D) + 1e-5f);

    for (int i = tid; i < D; i += blockDim.x) {
        float o = (buf[i] - mu) * rstd * g[i] + beta[i];
        xr[i] = o;
        xr16[i] = __float2half(o);
    }
}

// ---------------- in-place log_softmax over vocab ----------------------------
__global__ void log_softmax_kernel(float* __restrict__ out) {
    float* row = out + (size_t)blockIdx.x * V;
    __shared__ float red[32];
    const int tid = threadIdx.x;

    float m = -INFINITY, s = 0.0f;
    for (int i = tid; i < V; i += blockDim.x) {
        float v = row[i];
        if (v > m) { s = s * expf(m - v) + 1.0f; m = v; }
        else s += expf(v - m);
    }
    float M = block_max(m, red);
    float sum = block_sum(s * expf(m - M), red);
    const float lse = M + logf(sum);

    for (int i = tid; i < V; i += blockDim.x) row[i] -= lse;
}

// ---------------- launch -------------------------------------------------------
extern "C" void kernel_launch(void* const* d_in, const int* in_sizes, int n_in,
                              void* d_out, int out_size) {
    const int*   tokens = (const int*)  d_in[0];
    const float* embed  = (const float*)d_in[1];
    const float* Wq     = (const float*)d_in[2];
    const float* bq     = (const float*)d_in[3];
    const float* Wk     = (const float*)d_in[4];
    const float* bk     = (const float*)d_in[5];
    const float* Wv     = (const float*)d_in[6];
    const float* bv     = (const float*)d_in[7];
    const float* g1     = (const float*)d_in[8];
    const float* beta1  = (const float*)d_in[9];
    const float* W1     = (const float*)d_in[10];
    const float* bf1    = (const float*)d_in[11];
    const float* W2     = (const float*)d_in[12];
    const float* bf2    = (const float*)d_in[13];
    const float* g2     = (const float*)d_in[14];
    const float* beta2  = (const float*)d_in[15];
    const float* Wout   = (const float*)d_in[16];
    const float* bout   = (const float*)d_in[17];
    float* out = (float*)d_out;

    float *x, *attn, *scores;
    __half *x16, *qkv16, *v16T, *probs16, *h16, *wqkv16, *w1T16, *w2T16, *wout16;
    cudaGetSymbolAddress((void**)&x,       g_x);
    cudaGetSymbolAddress((void**)&x16,     g_x16);
    cudaGetSymbolAddress((void**)&qkv16,   g_qkv16);
    cudaGetSymbolAddress((void**)&v16T,    g_v16T);
    cudaGetSymbolAddress((void**)&attn,    g_attn);
    cudaGetSymbolAddress((void**)&scores,  g_scores);
    cudaGetSymbolAddress((void**)&probs16, g_probs16);
    cudaGetSymbolAddress((void**)&h16,     g_h16);
    cudaGetSymbolAddress((void**)&wqkv16,  g_wqkv16);
    cudaGetSymbolAddress((void**)&w1T16,   g_w1T16);
    cudaGetSymbolAddress((void**)&w2T16,   g_w2T16);
    cudaGetSymbolAddress((void**)&wout16,  g_wout16);
    __half* q16 = qkv16;
    __half* k16 = qkv16 + (size_t)BT * D;
    __half* v16 = qkv16 + (size_t)2 * BT * D;

    cudaFuncSetAttribute(gemm16<0, false, true,  true,  256>, cudaFuncAttributeMaxDynamicSharedMemorySize, SMEM256);
    cudaFuncSetAttribute(gemm16<0, true,  true,  true,  256>, cudaFuncAttributeMaxDynamicSharedMemorySize, SMEM256);
    cudaFuncSetAttribute(gemm16<0, false, true,  false, 256>, cudaFuncAttributeMaxDynamicSharedMemorySize, SMEM256);
    cudaFuncSetAttribute(gemm16<1, false, false, false, 128>, cudaFuncAttributeMaxDynamicSharedMemorySize, SMEM128);
    cudaFuncSetAttribute(gemm16<2, false, false, false, 128>, cudaFuncAttributeMaxDynamicSharedMemorySize, SMEM128);

    // ---- weight transposes to [N,K] K-major fp16 ----
    dim3 tb(32, 8);
    transpose_f2h_kernel<<<dim3(D / 32, D / 32, L), tb>>>(Wq, wqkv16 + 0 * (size_t)D * D, D, D, (long)D * D, (long)3 * D * D);
    transpose_f2h_kernel<<<dim3(D / 32, D / 32, L), tb>>>(Wk, wqkv16 + 1 * (size_t)D * D, D, D, (long)D * D, (long)3 * D * D);
    transpose_f2h_kernel<<<dim3(D / 32, D / 32, L), tb>>>(Wv, wqkv16 + 2 * (size_t)D * D, D, D, (long)D * D, (long)3 * D * D);
    transpose_f2h_kernel<<<dim3(DF / 32, D / 32, L), tb>>>(W1, w1T16, D, DF, (long)D * DF, (long)DF * D);
    transpose_f2h_kernel<<<dim3(D / 32, DF / 32, L), tb>>>(W2, w2T16, DF, D, (long)DF * D, (long)D * DF);
    transpose_f2h_kernel<<<dim3(V / 32, D / 32, 1), tb>>>(Wout, wout16, D, V, 0, 0);

    embed_pe_kernel<<<BT, 256>>>(tokens, embed, x, x16);

    for (int l = 0; l < L; ++l) {
        // fused QKV -> fp16 (z = 0,1,2 selects weight slice + bias + out slice)
        gemm16<0, false, true, true, 256><<<dim3(D / 256, BT / 128, 3), 256, SMEM256>>>(
            x16, wqkv16 + (size_t)l * 3 * D * D,
            bq + (size_t)l * D, bk + (size_t)l * D, bv + (size_t)l * D,
            qkv16, D, D, 0, (long)D * D, (long)BT * D);

        // scores = q @ k^T per batch -> fp32 (causal tile skip)
        gemm16<1, false, false, false, 128><<<dim3(T / 128, T / 128, B), 256, SMEM128>>>(
            q16, k16, nullptr, nullptr, nullptr,
            scores, T, D, (long)T * D, (long)T * D, (long)T * T);

        softmax_causal_kernel<<<dim3(T, B, 1), 256>>>(scores, probs16);

        // v^T per batch: [T,D] -> [D,T] (fp16)
        transpose_h2h_kernel<<<dim3(D / 32, T / 32, B), tb>>>(v16, v16T, T, D, (long)T * D, (long)D * T);

        // attn = probs @ v -> fp32 (K truncated at bm+128)
        gemm16<2, false, false, false, 128><<<dim3(D / 128, T / 128, B), 256, SMEM128>>>(
            probs16, v16T, nullptr, nullptr, nullptr,
            attn, D, T, (long)T * T, (long)D * T, (long)T * D);

        add_ln_kernel<<<BT, 256>>>(x, x16, attn, g1 + (size_t)l * D, beta1 + (size_t)l * D);

        // FFN1 -> fp16 h (relu)
        gemm16<0, true, true, true, 256><<<dim3(DF / 256, BT / 128, 1), 256, SMEM256>>>(
            x16, w1T16 + (size_t)l * DF * D,
            bf1 + (size_t)l * DF, nullptr, nullptr,
            h16, DF, D, 0, 0, 0);
        // FFN2 -> fp32 attn
        gemm16<0, false, true, false, 256><<<dim3(D / 256, BT / 128, 1), 256, SMEM256>>>(
            h16, w2T16 + (size_t)l * D * DF,
            bf2 + (size_t)l * D, nullptr, nullptr,
            attn, D, DF, 0, 0, 0);

        add_ln_kernel<<<BT, 256>>>(x, x16, attn, g2 + (size_t)l * D, beta2 + (size_t)l * D);
    }

    // vocab projection -> fp32 out
    gemm16<0, false, true, false, 256><<<dim3(V / 256, BT / 128, 1), 256, SMEM256>>>(
        x16, wout16, bout, nullptr, nullptr,
        out, V, D, 0, 0, 0);
    log_softmax_kernel<<<BT, 256>>>(out);
}

// round 9
// speedup vs baseline: 1.0803x; 1.0803x over previous
#include <cuda_runtime.h>
#include <cuda_fp16.h>
#include <math.h>
#include <stdint.h>

#define B 2
#define T 2048
#define V 32000
#define D 1024
#define DF 4096
#define L 6
#define BT (B*T)

// ---------------- scratch (device globals; no allocation allowed) ----------
__device__ __align__(1024) float  g_x[(size_t)BT * D];
__device__ __align__(1024) __half g_x16[(size_t)BT * D];
__device__ __align__(1024) __half g_qkv16[(size_t)3 * BT * D];
__device__ __align__(1024) __half g_v16T[(size_t)BT * D];
__device__ __align__(1024) float  g_attn[(size_t)BT * D];
__device__ __align__(1024) float  g_scores[(size_t)B * T * T];
__device__ __align__(1024) __half g_probs16[(size_t)B * T * T];
__device__ __align__(1024) __half g_h16[(size_t)BT * DF];
__device__ __align__(1024) __half g_wqkv16[(size_t)L * 3 * D * D];
__device__ __align__(1024) __half g_w1T16[(size_t)L * DF * D];
__device__ __align__(1024) __half g_w2T16[(size_t)L * D * DF];
__device__ __align__(1024) __half g_wout16[(size_t)V * D];

// ---------------- low-level helpers -----------------------------------------
__device__ __forceinline__ uint32_t smem_u32(const void* p) {
    uint32_t a;
    asm("{ .reg .u64 t; cvta.to.shared.u64 t, %1; cvt.u32.u64 %0, t; }" : "=r"(a) : "l"(p));
    return a;
}
__device__ __forceinline__ void cp16(void* smem_dst, const void* gmem_src) {
    uint32_t s = (uint32_t)__cvta_generic_to_shared(smem_dst);
    asm volatile("cp.async.cg.shared.global [%0], [%1], 16;" :: "r"(s), "l"(gmem_src));
}
__device__ __forceinline__ void cp_commit() {
    asm volatile("cp.async.commit_group;" ::: "memory");
}
template<int N>
__device__ __forceinline__ void cp_wait() {
    asm volatile("cp.async.wait_group %0;" :: "n"(N) : "memory");
}
__device__ __forceinline__ void ldsm4(uint32_t addr, uint32_t& r0, uint32_t& r1,
                                      uint32_t& r2, uint32_t& r3) {
    asm volatile("ldmatrix.sync.aligned.m8n8.x4.shared.b16 {%0,%1,%2,%3}, [%4];"
                 : "=r"(r0), "=r"(r1), "=r"(r2), "=r"(r3) : "r"(addr));
}

__device__ __forceinline__ float block_sum(float v, float* red) {
    int tid = threadIdx.x, lane = tid & 31, warp = tid >> 5;
    int nw = blockDim.x >> 5;
    #pragma unroll
    for (int o = 16; o; o >>= 1) v += __shfl_xor_sync(0xffffffffu, v, o);
    if (lane == 0) red[warp] = v;
    __syncthreads();
    float r = (tid < nw) ? red[tid] : 0.0f;
    if (warp == 0) {
        #pragma unroll
        for (int o = 16; o; o >>= 1) r += __shfl_xor_sync(0xffffffffu, r, o);
        if (tid == 0) red[0] = r;
    }
    __syncthreads();
    float out = red[0];
    __syncthreads();
    return out;
}
__device__ __forceinline__ float block_max(float v, float* red) {
    int tid = threadIdx.x, lane = tid & 31, warp = tid >> 5;
    int nw = blockDim.x >> 5;
    #pragma unroll
    for (int o = 16; o; o >>= 1) v = fmaxf(v, __shfl_xor_sync(0xffffffffu, v, o));
    if (lane == 0) red[warp] = v;
    __syncthreads();
    float r = (tid < nw) ? red[tid] : -INFINITY;
    if (warp == 0) {
        #pragma unroll
        for (int o = 16; o; o >>= 1) r = fmaxf(r, __shfl_xor_sync(0xffffffffu, r, o));
        if (tid == 0) red[0] = r;
    }
    __syncthreads();
    float out = red[0];
    __syncthreads();
    return out;
}

// ---------------- embed + positional encoding -------------------------------
__global__ void embed_pe_kernel(const int* __restrict__ tokens,
                                const float* __restrict__ embed,
                                float* __restrict__ x, __half* __restrict__ x16) {
    const int row = blockIdx.x;
    const int t = row % T;
    const int tok = tokens[row];
    const float* erow = embed + (size_t)tok * D;
    float* xrow = x + (size_t)row * D;
    __half* xrow16 = x16 + (size_t)row * D;
    for (int i = threadIdx.x; i < D; i += blockDim.x) {
        int ip = i & ~1;
        double freq = exp(((double)ip / (double)D) * log(10000.0));
        double angle = (double)t / freq;
        float pe = (i & 1) ? (float)cos(angle) : (float)sin(angle);
        float v = erow[i] + pe;
        xrow[i] = v;
        xrow16[i] = __float2half(v);
    }
}

// ---------------- transpose fp32 -> fp16 [R,C] -> [C,R], batched -------------
__global__ void transpose_f2h_kernel(const float* __restrict__ in, __half* __restrict__ out,
                                     int R, int C, long inStride, long outStride) {
    __shared__ float tile[32][33];
    const long zi = blockIdx.z;
    in  += zi * inStride;
    out += zi * outStride;
    const int c0 = blockIdx.x * 32, r0 = blockIdx.y * 32;
    const int tx = threadIdx.x, ty = threadIdx.y;   // 32 x 8
    #pragma unroll
    for (int j = 0; j < 32; j += 8)
        tile[ty + j][tx] = in[(long)(r0 + ty + j) * C + c0 + tx];
    __syncthreads();
    #pragma unroll
    for (int j = 0; j < 32; j += 8)
        out[(long)(c0 + ty + j) * R + r0 + tx] = __float2half(tile[tx][ty + j]);
}

// ---------------- transpose fp16 -> fp16 [R,C] -> [C,R], batched -------------
__global__ void transpose_h2h_kernel(const __half* __restrict__ in, __half* __restrict__ out,
                                     int R, int C, long inStride, long outStride) {
    __shared__ __half tile[32][36];
    const long zi = blockIdx.z;
    in  += zi * inStride;
    out += zi * outStride;
    const int c0 = blockIdx.x * 32, r0 = blockIdx.y * 32;
    const int tx = threadIdx.x, ty = threadIdx.y;   // 32 x 8
    #pragma unroll
    for (int j = 0; j < 32; j += 8)
        tile[ty + j][tx] = in[(long)(r0 + ty + j) * C + c0 + tx];
    __syncthreads();
    #pragma unroll
    for (int j = 0; j < 32; j += 8)
        out[(long)(c0 + ty + j) * R + r0 + tx] = tile[tx][ty + j];
}

// ---------------- FP16 mma.sync TT GEMM --------------------------------------
// C[M,N] = A[M,K] @ Bt[N,K]^T (+bias)(+relu). A,Bt fp16 K-major, fp32 accum.
// 128x128 CTA tile, BK=32 (2x k16), 4-stage cp.async, 8 warps (32x64 per warp).
// CAUSAL: 0 none, 1 skip tiles above diagonal, 2 K truncated at bm+128.
// OUT16: write __half C, else float C.
#define RST 40                                  // halves per smem row (80 B)
#define STAGE_H (256 * RST)                     // halves per stage (A 128 + B 128)
#define NSTAGE 4
#define GEMM_SMEM16 (NSTAGE * STAGE_H * 2)      // 81920 B

template<int CAUSAL, bool RELU, bool BIAS, bool OUT16>
__global__ __launch_bounds__(256, 2) void gemm16(
    const __half* __restrict__ A, const __half* __restrict__ Bt,
    const float* __restrict__ b0, const float* __restrict__ b1, const float* __restrict__ b2,
    void* __restrict__ Cv, int N, int K, long sA, long sB, long sC)
{
    extern __shared__ __half smh[];

    const int bm = blockIdx.y * 128;
    const int bn = blockIdx.x * 128;
    if (CAUSAL == 1 && bn > bm + 127) return;
    const int z = blockIdx.z;
    A  += (long)z * sA;
    Bt += (long)z * sB;

    const int tid = threadIdx.x, warp = tid >> 5, lane = tid & 31;
    const int g = lane >> 2, cg = lane & 3;
    const int wm = (warp >> 1) * 32, wn = (warp & 1) * 64;

    const int Kend = (CAUSAL == 2) ? min(K, bm + 128) : K;
    const int KT = Kend >> 5;

    const uint32_t sbase = smem_u32(smh);

    // ldmatrix.x4 per-lane byte offsets within a stage (canonical m16n8k16 map)
    uint32_t aoff[2], boff[4];
    #pragma unroll
    for (int mi = 0; mi < 2; mi++)
        aoff[mi] = (uint32_t)((wm + mi * 16 + (lane & 15)) * RST * 2 + (lane >> 4) * 16);
    #pragma unroll
    for (int np = 0; np < 4; np++)
        boff[np] = (uint32_t)((128 + wn + np * 16 + (lane & 15)) * RST * 2 + (lane >> 4) * 16);

    auto issue = [&](int s) {
        if (s >= KT) { cp_commit(); return; }
        const int k0 = s << 5;
        __half* As = smh + (s % NSTAGE) * STAGE_H;
        __half* Bs = As + 128 * RST;
        #pragma unroll
        for (int i = 0; i < 2; i++) {
            int idx = tid + i * 256;
            int r = idx >> 2, c = (idx & 3) * 8;
            cp16(&As[r * RST + c], A + (long)(bm + r) * K + k0 + c);
            cp16(&Bs[r * RST + c], Bt + (long)(bn + r) * K + k0 + c);
        }
        cp_commit();
    };

    float acc[2][8][4];
    #pragma unroll
    for (int mi = 0; mi < 2; mi++)
        #pragma unroll
        for (int ni = 0; ni < 8; ni++)
            #pragma unroll
            for (int j = 0; j < 4; j++) acc[mi][ni][j] = 0.0f;

    auto comp = [&](int slot) {
        const uint32_t st = sbase + (uint32_t)slot * (STAGE_H * 2);
        #pragma unroll
        for (int ks = 0; ks < 2; ks++) {
            uint32_t af[2][4];
            uint32_t bf[8][2];
            #pragma unroll
            for (int mi = 0; mi < 2; mi++)
                ldsm4(st + aoff[mi] + ks * 32, af[mi][0], af[mi][1], af[mi][2], af[mi][3]);
            #pragma unroll
            for (int np = 0; np < 4; np++) {
                uint32_t q0, q1, q2, q3;
                ldsm4(st + boff[np] + ks * 32, q0, q1, q2, q3);
                bf[2 * np][0] = q0; bf[2 * np][1] = q2;
                bf[2 * np + 1][0] = q1; bf[2 * np + 1][1] = q3;
            }
            #pragma unroll
            for (int mi = 0; mi < 2; mi++)
                #pragma unroll
                for (int ni = 0; ni < 8; ni++)
                    asm volatile(
                        "mma.sync.aligned.m16n8k16.row.col.f32.f16.f16.f32 "
                        "{%0,%1,%2,%3}, {%4,%5,%6,%7}, {%8,%9}, {%0,%1,%2,%3};"
                        : "+f"(acc[mi][ni][0]), "+f"(acc[mi][ni][1]),
                          "+f"(acc[mi][ni][2]), "+f"(acc[mi][ni][3])
                        : "r"(af[mi][0]), "r"(af[mi][1]), "r"(af[mi][2]), "r"(af[mi][3]),
                          "r"(bf[ni][0]), "r"(bf[ni][1]));
        }
    };

    issue(0);
    issue(1);
    issue(2);
    for (int i = 0; i < KT; i++) {
        cp_wait<2>();
        __syncthreads();
        issue(i + 3);
        comp(i % NSTAGE);
    }

    // epilogue
    const float* bias = BIAS ? (z == 0 ? b0 : (z == 1 ? b1 : b2)) : b0;
    float*  Cf = (float*)Cv  + (long)z * sC;
    __half* Ch = (__half*)Cv + (long)z * sC;
    #pragma unroll
    for (int mi = 0; mi < 2; mi++) {
        const long r0 = bm + wm + mi * 16 + g;
        #pragma unroll
        for (int ni = 0; ni < 8; ni++) {
            const int col = bn + wn + ni * 8 + cg * 2;
            float bb0 = 0.0f, bb1 = 0.0f;
            if (BIAS) { bb0 = bias[col]; bb1 = bias[col + 1]; }
            float2 v0 = make_float2(acc[mi][ni][0] + bb0, acc[mi][ni][1] + bb1);
            float2 v1 = make_float2(acc[mi][ni][2] + bb0, acc[mi][ni][3] + bb1);
            if (RELU) {
                v0.x = fmaxf(v0.x, 0.0f); v0.y = fmaxf(v0.y, 0.0f);
                v1.x = fmaxf(v1.x, 0.0f); v1.y = fmaxf(v1.y, 0.0f);
            }
            if (OUT16) {
                *(__half2*)(Ch + r0 * N + col)       = __floats2half2_rn(v0.x, v0.y);
                *(__half2*)(Ch + (r0 + 8) * N + col) = __floats2half2_rn(v1.x, v1.y);
            } else {
                *(float2*)(Cf + r0 * N + col)       = v0;
                *(float2*)(Cf + (r0 + 8) * N + col) = v1;
            }
        }
    }
}

// ---------------- causal softmax: fp32 scores -> fp16 probs ------------------
__global__ void softmax_causal_kernel(const float* __restrict__ scores,
                                      __half* __restrict__ probs) {
    const int t = blockIdx.x;
    const int b = blockIdx.y;
    const float* row = scores + ((size_t)b * T + t) * T;
    __half* prow = probs + ((size_t)b * T + t) * T;
    const int n = t + 1;
    const float inv_scale = 0.03125f;   // 1/sqrt(1024)
    __shared__ float red[32];
    const int tid = threadIdx.x;

    float m = -INFINITY;
    for (int s = tid; s < n; s += blockDim.x) m = fmaxf(m, row[s] * inv_scale);
    m = block_max(m, red);

    float sum = 0.0f;
    for (int s = tid; s < n; s += blockDim.x) sum += expf(row[s] * inv_scale - m);
    sum = block_sum(sum, red);
    const float inv = 1.0f / sum;

    for (int s = tid; s < n; s += blockDim.x)
        prow[s] = __float2half(expf(row[s] * inv_scale - m) * inv);
    for (int s = n + tid; s < T; s += blockDim.x) prow[s] = __float2half(0.0f);
}

// ---------------- x = LayerNorm(x + y) * g + beta  (fp32 + fp16 out) ---------
__global__ void add_ln_kernel(float* __restrict__ x, __half* __restrict__ x16,
                              const float* __restrict__ y,
                              const float* __restrict__ g, const float* __restrict__ beta) {
    const int row = blockIdx.x;
    __shared__ float buf[D];
    __shared__ float red[32];
    float* xr = x + (size_t)row * D;
    __half* xr16 = x16 + (size_t)row * D;
    const float* yr = y + (size_t)row * D;
    const int tid = threadIdx.x;

    float sum = 0.0f;
    for (int i = tid; i < D; i += blockDim.x) {
        float v = xr[i] + yr[i];
        buf[i] = v;
        sum += v;
    }
    __syncthreads();
    sum = block_sum(sum, red);
    const float mu = sum * (1.0f / D);

    float vs = 0.0f;
    for (int i = tid; i < D; i += blockDim.x) {
        float d = buf[i] - mu;
        vs += d * d;
    }
    vs = block_sum(vs, red);
    const float rstd = rsqrtf(vs * (1.0f / D) + 1e-5f);

    for (int i = tid; i < D; i += blockDim.x) {
        float o = (buf[i] - mu) * rstd * g[i] + beta[i];
        xr[i] = o;
        xr16[i] = __float2half(o);
    }
}

// ---------------- in-place log_softmax over vocab ----------------------------
__global__ void log_softmax_kernel(float* __restrict__ out) {
    float* row = out + (size_t)blockIdx.x * V;
    __shared__ float red[32];
    const int tid = threadIdx.x;

    float m = -INFINITY, s = 0.0f;
    for (int i = tid; i < V; i += blockDim.x) {
        float v = row[i];
        if (v > m) { s = s * expf(m - v) + 1.0f; m = v; }
        else s += expf(v - m);
    }
    float M = block_max(m, red);
    float sum = block_sum(s * expf(m - M), red);
    const float lse = M + logf(sum);

    for (int i = tid; i < V; i += blockDim.x) row[i] -= lse;
}

// ---------------- launch -------------------------------------------------------
extern "C" void kernel_launch(void* const* d_in, const int* in_sizes, int n_in,
                              void* d_out, int out_size) {
    const int*   tokens = (const int*)  d_in[0];
    const float* embed  = (const float*)d_in[1];
    const float* Wq     = (const float*)d_in[2];
    const float* bq     = (const float*)d_in[3];
    const float* Wk     = (const float*)d_in[4];
    const float* bk     = (const float*)d_in[5];
    const float* Wv     = (const float*)d_in[6];
    const float* bv     = (const float*)d_in[7];
    const float* g1     = (const float*)d_in[8];
    const float* beta1  = (const float*)d_in[9];
    const float* W1     = (const float*)d_in[10];
    const float* bf1    = (const float*)d_in[11];
    const float* W2     = (const float*)d_in[12];
    const float* bf2    = (const float*)d_in[13];
    const float* g2     = (const float*)d_in[14];
    const float* beta2  = (const float*)d_in[15];
    const float* Wout   = (const float*)d_in[16];
    const float* bout   = (const float*)d_in[17];
    float* out = (float*)d_out;

    float *x, *attn, *scores;
    __half *x16, *qkv16, *v16T, *probs16, *h16, *wqkv16, *w1T16, *w2T16, *wout16;
    cudaGetSymbolAddress((void**)&x,       g_x);
    cudaGetSymbolAddress((void**)&x16,     g_x16);
    cudaGetSymbolAddress((void**)&qkv16,   g_qkv16);
    cudaGetSymbolAddress((void**)&v16T,    g_v16T);
    cudaGetSymbolAddress((void**)&attn,    g_attn);
    cudaGetSymbolAddress((void**)&scores,  g_scores);
    cudaGetSymbolAddress((void**)&probs16, g_probs16);
    cudaGetSymbolAddress((void**)&h16,     g_h16);
    cudaGetSymbolAddress((void**)&wqkv16,  g_wqkv16);
    cudaGetSymbolAddress((void**)&w1T16,   g_w1T16);
    cudaGetSymbolAddress((void**)&w2T16,   g_w2T16);
    cudaGetSymbolAddress((void**)&wout16,  g_wout16);
    __half* q16 = qkv16;
    __half* k16 = qkv16 + (size_t)BT * D;
    __half* v16 = qkv16 + (size_t)2 * BT * D;

    cudaFuncSetAttribute(gemm16<0, false, true,  true>,  cudaFuncAttributeMaxDynamicSharedMemorySize, GEMM_SMEM16);
    cudaFuncSetAttribute(gemm16<0, true,  true,  true>,  cudaFuncAttributeMaxDynamicSharedMemorySize, GEMM_SMEM16);
    cudaFuncSetAttribute(gemm16<0, false, true,  false>, cudaFuncAttributeMaxDynamicSharedMemorySize, GEMM_SMEM16);
    cudaFuncSetAttribute(gemm16<1, false, false, false>, cudaFuncAttributeMaxDynamicSharedMemorySize, GEMM_SMEM16);
    cudaFuncSetAttribute(gemm16<2, false, false, false>, cudaFuncAttributeMaxDynamicSharedMemorySize, GEMM_SMEM16);

    // ---- weight transposes to [N,K] K-major fp16 ----
    dim3 tb(32, 8);
    transpose_f2h_kernel<<<dim3(D / 32, D / 32, L), tb>>>(Wq, wqkv16 + 0 * (size_t)D * D, D, D, (long)D * D, (long)3 * D * D);
    transpose_f2h_kernel<<<dim3(D / 32, D / 32, L), tb>>>(Wk, wqkv16 + 1 * (size_t)D * D, D, D, (long)D * D, (long)3 * D * D);
    transpose_f2h_kernel<<<dim3(D / 32, D / 32, L), tb>>>(Wv, wqkv16 + 2 * (size_t)D * D, D, D, (long)D * D, (long)3 * D * D);
    transpose_f2h_kernel<<<dim3(DF / 32, D / 32, L), tb>>>(W1, w1T16, D, DF, (long)D * DF, (long)DF * D);
    transpose_f2h_kernel<<<dim3(D / 32, DF / 32, L), tb>>>(W2, w2T16, DF, D, (long)DF * D, (long)D * DF);
    transpose_f2h_kernel<<<dim3(V / 32, D / 32, 1), tb>>>(Wout, wout16, D, V, 0, 0);

    embed_pe_kernel<<<BT, 256>>>(tokens, embed, x, x16);

    for (int l = 0; l < L; ++l) {
        // fused QKV -> fp16 (z = 0,1,2 selects weight slice + bias + out slice)
        gemm16<0, false, true, true><<<dim3(D / 128, BT / 128, 3), 256, GEMM_SMEM16>>>(
            x16, wqkv16 + (size_t)l * 3 * D * D,
            bq + (size_t)l * D, bk + (size_t)l * D, bv + (size_t)l * D,
            qkv16, D, D, 0, (long)D * D, (long)BT * D);

        // scores = q @ k^T per batch -> fp32 (causal tile skip)
        gemm16<1, false, false, false><<<dim3(T / 128, T / 128, B), 256, GEMM_SMEM16>>>(
            q16, k16, nullptr, nullptr, nullptr,
            scores, T, D, (long)T * D, (long)T * D, (long)T * T);

        softmax_causal_kernel<<<dim3(T, B, 1), 256>>>(scores, probs16);

        // v^T per batch: [T,D] -> [D,T] (fp16)
        transpose_h2h_kernel<<<dim3(D / 32, T / 32, B), tb>>>(v16, v16T, T, D, (long)T * D, (long)D * T);

        // attn = probs @ v -> fp32 (K truncated at bm+128)
        gemm16<2, false, false, false><<<dim3(D / 128, T / 128, B), 256, GEMM_SMEM16>>>(
            probs16, v16T, nullptr, nullptr, nullptr,
            attn, D, T, (long)T * T, (long)D * T, (long)T * D);

        add_ln_kernel<<<BT, 256>>>(x, x16, attn, g1 + (size_t)l * D, beta1 + (size_t)l * D);

        // FFN1 -> fp16 h (relu)
        gemm16<0, true, true, true><<<dim3(DF / 128, BT / 128, 1), 256, GEMM_SMEM16>>>(
            x16, w1T16 + (size_t)l * DF * D,
            bf1 + (size_t)l * DF, nullptr, nullptr,
            h16, DF, D, 0, 0, 0);
        // FFN2 -> fp32 attn
        gemm16<0, false, true, false><<<dim3(D / 128, BT / 128, 1), 256, GEMM_SMEM16>>>(
            h16, w2T16 + (size_t)l * D * DF,
            bf2 + (size_t)l * D, nullptr, nullptr,
            attn, D, DF, 0, 0, 0);

        add_ln_kernel<<<BT, 256>>>(x, x16, attn, g2 + (size_t)l * D, beta2 + (size_t)l * D);
    }

    // vocab projection -> fp32 out
    gemm16<0, false, true, false><<<dim3(V / 128, BT / 128, 1), 256, GEMM_SMEM16>>>(
        x16, wout16, bout, nullptr, nullptr,
        out, V, D, 0, 0, 0);
    log_softmax_kernel<<<BT, 256>>>(out);
}